// round 1
// baseline (speedup 1.0000x reference)
#include <cuda_runtime.h>
#include <cuda_bf16.h>

// TelephotoInterp: rotate/shift/drift particles (telephoto branch) or passthrough
// (inside branch), then CIC-paint z-slab-selected particles onto [res,res] grid.
//
// Inputs (metadata order):
//  0 positions  [N,3] f32
//  1 velocities [N,3] f32
//  2 rotations  [47,3,3] f32
//  3 observer   [3] f32
//  4 r_centers  [4] f32
//  5 density_widths [4] f32
//  6 t          [] f32
//  7 max_comoving_distance [] f32
//  8 box_size   [] f32
//  9 shell_idx  [] i32
// 10 rotation_idx [] i32
// 11 grid_res   [] i32
// out: [res*res] f32

__global__ void telephoto_paint_kernel(
    const float* __restrict__ pos,
    const float* __restrict__ vel,
    const float* __restrict__ rotations,
    const float* __restrict__ observer,
    const float* __restrict__ r_centers,
    const float* __restrict__ widths,
    const float* __restrict__ t_p,
    const float* __restrict__ maxd_p,
    const float* __restrict__ box_p,
    const int*   __restrict__ shell_p,
    const int*   __restrict__ rotidx_p,
    const int*   __restrict__ res_p,
    float* __restrict__ out,
    int n)
{
    const int i = blockIdx.x * blockDim.x + threadIdx.x;
    if (i >= n) return;

    // Scalar params (broadcast loads, L1-cached)
    const int   shell = shell_p[0];
    const float rc    = r_centers[shell];
    const float w     = widths[shell];
    const float maxd  = maxd_p[0];
    const float box   = box_p[0];
    const int   res   = res_p[0];
    const bool inside = (rc + 0.5f * w <= maxd);

    const float ox = observer[0], oy = observer[1], oz = observer[2];

    const float px = pos[3*i + 0];
    const float py = pos[3*i + 1];
    const float pz = pos[3*i + 2];

    float X, Y, Z;
    if (inside) {
        X = px; Y = py; Z = pz;
    } else {
        const int ridx = rotidx_p[0] % 47;
        const float* __restrict__ M = rotations + 9 * ridx;
        const float m00 = M[0], m01 = M[1], m02 = M[2];
        const float m10 = M[3], m11 = M[4], m12 = M[5];
        const float m20 = M[6], m21 = M[7], m22 = M[8];
        const float t = t_p[0];
        const float shift = floorf(rc / maxd) * maxd;

        const float qx = px - ox, qy = py - oy, qz = pz - oz;
        // p_rot = (pos - obs) @ M^T  -> row i of M dot q
        const float rx = m00*qx + m01*qy + m02*qz;
        const float ry = m10*qx + m11*qy + m12*qz;
        const float rz = m20*qx + m21*qy + m22*qz + shift;  // + z_axis*shift

        const float vx0 = vel[3*i + 0];
        const float vy0 = vel[3*i + 1];
        const float vz0 = vel[3*i + 2];
        const float vx = m00*vx0 + m01*vy0 + m02*vz0;
        const float vy = m10*vx0 + m11*vy0 + m12*vz0;
        const float vz = m20*vx0 + m21*vy0 + m22*vz0;

        // dist = |p_shift - observer|
        const float dxd = rx - ox, dyd = ry - oy, dzd = rz - oz;
        const float dist = sqrtf(dxd*dxd + dyd*dyd + dzd*dzd);

        const float a_tgt = 1.0f / (1.0f + dist / 3000.0f);
        const float gp_a  = a_tgt * sqrtf(a_tgt);   // a^1.5
        const float gp_t  = t * sqrtf(t);           // t^1.5
        const float sq_ac = sqrtf(sqrtf(t * a_tgt)); // sqrt(ac), ac = sqrt(t*a)
        const float drift = (gp_a - gp_t) / (1.5f * sq_ac);

        // p_drift + observer
        X = rx + drift * vx + ox;
        Y = ry + drift * vy + oy;
        Z = rz + drift * vz + oz;
    }

    // z-slab selection: sel==0 particles contribute +0.0 -> skip entirely
    if (!(Z >= rc - 0.5f * w && Z < rc + 0.5f * w)) return;

    const float scale = (float)res / box;
    const float xg = X * scale;
    const float yg = Y * scale;
    const float fx0 = floorf(xg);
    const float fy0 = floorf(yg);
    const float fx = xg - fx0;
    const float fy = yg - fy0;

    int ix0 = (int)fx0 % res; if (ix0 < 0) ix0 += res;
    int iy0 = (int)fy0 % res; if (iy0 < 0) iy0 += res;
    int ix1 = ix0 + 1; if (ix1 == res) ix1 = 0;
    int iy1 = iy0 + 1; if (iy1 == res) iy1 = 0;

    const float w00 = (1.0f - fx) * (1.0f - fy);
    const float w10 = fx * (1.0f - fy);
    const float w01 = (1.0f - fx) * fy;
    const float w11 = fx * fy;

    atomicAdd(&out[ix0 * res + iy0], w00);
    atomicAdd(&out[ix1 * res + iy0], w10);
    atomicAdd(&out[ix0 * res + iy1], w01);
    atomicAdd(&out[ix1 * res + iy1], w11);
}

extern "C" void kernel_launch(void* const* d_in, const int* in_sizes, int n_in,
                              void* d_out, int out_size) {
    const float* positions  = (const float*)d_in[0];
    const float* velocities = (const float*)d_in[1];
    const float* rotations  = (const float*)d_in[2];
    const float* observer   = (const float*)d_in[3];
    const float* r_centers  = (const float*)d_in[4];
    const float* widths     = (const float*)d_in[5];
    const float* t_p        = (const float*)d_in[6];
    const float* maxd_p     = (const float*)d_in[7];
    const float* box_p      = (const float*)d_in[8];
    const int*   shell_p    = (const int*)d_in[9];
    const int*   rotidx_p   = (const int*)d_in[10];
    const int*   res_p      = (const int*)d_in[11];
    float* out = (float*)d_out;

    const int n = in_sizes[0] / 3;

    // Output is poisoned to 0xAA -> zero it (memset node is graph-capturable)
    cudaMemsetAsync(out, 0, (size_t)out_size * sizeof(float));

    const int threads = 256;
    const int blocks = (n + threads - 1) / threads;
    telephoto_paint_kernel<<<blocks, threads>>>(
        positions, velocities, rotations, observer, r_centers, widths,
        t_p, maxd_p, box_p, shell_p, rotidx_p, res_p, out, n);
}

// round 2
// speedup vs baseline: 1.2983x; 1.2983x over previous
#include <cuda_runtime.h>
#include <cuda_bf16.h>

// TelephotoInterp: rotate/shift/drift particles (telephoto branch) or passthrough
// (inside branch), then CIC-paint z-slab-selected particles onto [res,res] grid.
//
// R2: 4 particles/thread with float4 (LDG.128) loads; paired red.global.add.v2.f32
//     atomics when the y-pair is 8B-aligned (iy0 even -> no wrap possible, res even).

__device__ __forceinline__ void red_add_v2(float* addr, float a, float b) {
    asm volatile("red.global.add.v2.f32 [%0], {%1, %2};"
                 :: "l"(addr), "f"(a), "f"(b) : "memory");
}

__global__ void telephoto_paint_kernel(
    const float4* __restrict__ pos4,
    const float4* __restrict__ vel4,
    const float* __restrict__ rotations,
    const float* __restrict__ observer,
    const float* __restrict__ r_centers,
    const float* __restrict__ widths,
    const float* __restrict__ t_p,
    const float* __restrict__ maxd_p,
    const float* __restrict__ box_p,
    const int*   __restrict__ shell_p,
    const int*   __restrict__ rotidx_p,
    const int*   __restrict__ res_p,
    float* __restrict__ out,
    int n)   // n = number of particles
{
    const int t = blockIdx.x * blockDim.x + threadIdx.x;
    const int base = 4 * t;
    if (base >= n) return;

    // Scalar params (uniform broadcast loads)
    const int   shell = shell_p[0];
    const float rc    = r_centers[shell];
    const float w     = widths[shell];
    const float maxd  = maxd_p[0];
    const float box   = box_p[0];
    const int   res   = res_p[0];
    const bool inside = (rc + 0.5f * w <= maxd);
    const float ox = observer[0], oy = observer[1], oz = observer[2];
    const float zlo = rc - 0.5f * w;
    const float zhi = rc + 0.5f * w;
    const float scale = (float)res / box;

    // Rotation / drift params (only meaningful for telephoto branch)
    float m00=1.f,m01=0.f,m02=0.f,m10=0.f,m11=1.f,m12=0.f,m20=0.f,m21=0.f,m22=1.f;
    float tt = 0.f, shift = 0.f, gp_t = 0.f;
    if (!inside) {
        const int ridx = rotidx_p[0] % 47;
        const float* __restrict__ M = rotations + 9 * ridx;
        m00=M[0]; m01=M[1]; m02=M[2];
        m10=M[3]; m11=M[4]; m12=M[5];
        m20=M[6]; m21=M[7]; m22=M[8];
        tt = t_p[0];
        shift = floorf(rc / maxd) * maxd;
        gp_t = tt * sqrtf(tt);
    }

    // Vectorized loads: 4 particles = 12 floats = 3 float4 per array.
    // base is a multiple of 4 -> byte offset multiple of 48 -> 16B aligned.
    const float4 pA = pos4[3*t + 0];
    const float4 pB = pos4[3*t + 1];
    const float4 pC = pos4[3*t + 2];
    const float4 vA = vel4[3*t + 0];
    const float4 vB = vel4[3*t + 1];
    const float4 vC = vel4[3*t + 2];

    float px[4] = {pA.x, pA.w, pB.z, pC.y};
    float py[4] = {pA.y, pB.x, pB.w, pC.z};
    float pz[4] = {pA.z, pB.y, pC.x, pC.w};
    float vx[4] = {vA.x, vA.w, vB.z, vC.y};
    float vy[4] = {vA.y, vB.x, vB.w, vC.z};
    float vz[4] = {vA.z, vB.y, vC.x, vC.w};

    #pragma unroll
    for (int k = 0; k < 4; k++) {
        if (base + k >= n) break;

        float X, Y, Z;
        if (inside) {
            X = px[k]; Y = py[k]; Z = pz[k];
        } else {
            const float qx = px[k] - ox, qy = py[k] - oy, qz = pz[k] - oz;
            const float rx = m00*qx + m01*qy + m02*qz;
            const float ry = m10*qx + m11*qy + m12*qz;
            const float rz = m20*qx + m21*qy + m22*qz + shift;

            const float wx = m00*vx[k] + m01*vy[k] + m02*vz[k];
            const float wy = m10*vx[k] + m11*vy[k] + m12*vz[k];
            const float wz = m20*vx[k] + m21*vy[k] + m22*vz[k];

            const float dxd = rx - ox, dyd = ry - oy, dzd = rz - oz;
            const float dist = sqrtf(dxd*dxd + dyd*dyd + dzd*dzd);

            const float a_tgt = 1.0f / (1.0f + dist * (1.0f/3000.0f));
            const float gp_a  = a_tgt * sqrtf(a_tgt);    // a^1.5
            const float sq_ac = sqrtf(sqrtf(tt * a_tgt)); // sqrt(ac)
            const float drift = (gp_a - gp_t) / (1.5f * sq_ac);

            X = rx + drift * wx + ox;
            Y = ry + drift * wy + oy;
            Z = rz + drift * wz + oz;
        }

        // sel==0 contributes +0.0 in the reference -> skip
        if (!(Z >= zlo && Z < zhi)) continue;

        const float xg = X * scale;
        const float yg = Y * scale;
        const float fx0 = floorf(xg);
        const float fy0 = floorf(yg);
        const float fx = xg - fx0;
        const float fy = yg - fy0;

        int ix0 = (int)fx0 % res; if (ix0 < 0) ix0 += res;
        int iy0 = (int)fy0 % res; if (iy0 < 0) iy0 += res;
        int ix1 = ix0 + 1; if (ix1 == res) ix1 = 0;

        const float w00 = (1.0f - fx) * (1.0f - fy);
        const float w10 = fx * (1.0f - fy);
        const float w01 = (1.0f - fx) * fy;
        const float w11 = fx * fy;

        if ((iy0 & 1) == 0) {
            // iy1 = iy0+1, contiguous + 8B aligned (res even -> no wrap here)
            red_add_v2(&out[ix0 * res + iy0], w00, w01);
            red_add_v2(&out[ix1 * res + iy0], w10, w11);
        } else {
            int iy1 = iy0 + 1; if (iy1 == res) iy1 = 0;
            atomicAdd(&out[ix0 * res + iy0], w00);
            atomicAdd(&out[ix1 * res + iy0], w10);
            atomicAdd(&out[ix0 * res + iy1], w01);
            atomicAdd(&out[ix1 * res + iy1], w11);
        }
    }
}

extern "C" void kernel_launch(void* const* d_in, const int* in_sizes, int n_in,
                              void* d_out, int out_size) {
    const float* positions  = (const float*)d_in[0];
    const float* velocities = (const float*)d_in[1];
    const float* rotations  = (const float*)d_in[2];
    const float* observer   = (const float*)d_in[3];
    const float* r_centers  = (const float*)d_in[4];
    const float* widths     = (const float*)d_in[5];
    const float* t_p        = (const float*)d_in[6];
    const float* maxd_p     = (const float*)d_in[7];
    const float* box_p      = (const float*)d_in[8];
    const int*   shell_p    = (const int*)d_in[9];
    const int*   rotidx_p   = (const int*)d_in[10];
    const int*   res_p      = (const int*)d_in[11];
    float* out = (float*)d_out;

    const int n = in_sizes[0] / 3;

    cudaMemsetAsync(out, 0, (size_t)out_size * sizeof(float));

    const int threads = 256;
    const int nthreads_needed = (n + 3) / 4;
    const int blocks = (nthreads_needed + threads - 1) / threads;
    telephoto_paint_kernel<<<blocks, threads>>>(
        (const float4*)positions, (const float4*)velocities,
        rotations, observer, r_centers, widths,
        t_p, maxd_p, box_p, shell_p, rotidx_p, res_p, out, n);
}